// round 2
// baseline (speedup 1.0000x reference)
#include <cuda_runtime.h>

// Problem constants
#define B_ 4
#define S_ 2048
#define E_ 1024
#define H_ 8
#define O_ 128

// Scratch (allocation-free: __device__ globals)
__device__ float g_Q[(size_t)H_ * B_ * S_ * O_];   // (H,B,S,O)  32MB
__device__ float g_K[(size_t)B_ * S_ * O_];        // (B,S,O)     4MB
__device__ float g_V[(size_t)B_ * S_ * O_];        // (B,S,O)     4MB
__device__ float g_ctx[(size_t)B_ * S_ * H_ * O_]; // (B,S,H,O)  32MB

// ---------------------------------------------------------------------------
// Generic fp32 SGEMM: C[M,N] = A[M,K] * Bw[K,N], row-major.
// Tile 64(M) x 128(N) x 16(K), 256 threads, 4x8 micro-tile per thread.
// blockIdx.z selects a weight slice (Bw + z*sBz) and output slice (C + z*sCz).
// M % 64 == 0, N % 128 == 0, K % 16 == 0 (holds for all our shapes).
// ---------------------------------------------------------------------------
__global__ __launch_bounds__(256) void sgemm_kernel(
    const float* __restrict__ A, const float* __restrict__ Bw,
    float* __restrict__ C, int M, int N, int K,
    long long sBz, long long sCz)
{
    const float* Bp = Bw + (long long)blockIdx.z * sBz;
    float*       Cp = C  + (long long)blockIdx.z * sCz;

    __shared__ __align__(16) float As[16][68];   // transposed: As[k][m]
    __shared__ __align__(16) float Bs[16][132];

    const int t    = threadIdx.x;
    const int row0 = blockIdx.y * 64;
    const int col0 = blockIdx.x * 128;

    const int ar = t >> 2,  ak = (t & 3) << 2;   // A tile load: 64 rows x 16 cols
    const int br = t >> 4,  bc = (t & 15) << 3;  // B tile load: 16 rows x 128 cols
    const int ty = t >> 4,  tx = t & 15;         // compute mapping

    float acc[4][8];
#pragma unroll
    for (int i = 0; i < 4; i++)
#pragma unroll
        for (int j = 0; j < 8; j++) acc[i][j] = 0.f;

    for (int k0 = 0; k0 < K; k0 += 16) {
        // Load A tile (coalesced float4), store transposed
        float4 av = *(const float4*)&A[(long long)(row0 + ar) * K + k0 + ak];
        As[ak + 0][ar] = av.x;
        As[ak + 1][ar] = av.y;
        As[ak + 2][ar] = av.z;
        As[ak + 3][ar] = av.w;
        // Load B tile (coalesced float4 x2)
        const float* bg = &Bp[(long long)(k0 + br) * N + col0 + bc];
        *(float4*)&Bs[br][bc]     = *(const float4*)bg;
        *(float4*)&Bs[br][bc + 4] = *(const float4*)(bg + 4);
        __syncthreads();

#pragma unroll
        for (int kk = 0; kk < 16; kk++) {
            float4 a4 = *(const float4*)&As[kk][ty << 2];
            float4 b0 = *(const float4*)&Bs[kk][tx << 2];
            float4 b1 = *(const float4*)&Bs[kk][64 + (tx << 2)];
            float a[4]  = {a4.x, a4.y, a4.z, a4.w};
            float bv[8] = {b0.x, b0.y, b0.z, b0.w, b1.x, b1.y, b1.z, b1.w};
#pragma unroll
            for (int i = 0; i < 4; i++)
#pragma unroll
                for (int j = 0; j < 8; j++) acc[i][j] += a[i] * bv[j];
        }
        __syncthreads();
    }

#pragma unroll
    for (int i = 0; i < 4; i++) {
        float* cr = &Cp[(long long)(row0 + (ty << 2) + i) * N + col0];
        *(float4*)&cr[tx << 2] =
            make_float4(acc[i][0], acc[i][1], acc[i][2], acc[i][3]);
        *(float4*)&cr[64 + (tx << 2)] =
            make_float4(acc[i][4], acc[i][5], acc[i][6], acc[i][7]);
    }
}

// ---------------------------------------------------------------------------
// fp32 flash attention: grid (S/64, H, B), 512 threads.
// Q tile 64x128, K/V tiles 64x128, online softmax in fp32.
// Writes ctx in (B,S,H,O) layout so the output projection is a plain GEMM.
// ---------------------------------------------------------------------------
#define ATTN_SMEM_FLOATS (3 * 64 * 132 + 64 * 68 + 3 * 64)

__global__ __launch_bounds__(512) void attn_kernel()
{
    extern __shared__ __align__(16) float sm[];
    float* Qs   = sm;                 // 64 x 132
    float* Ks   = Qs + 64 * 132;      // 64 x 132
    float* Vs   = Ks + 64 * 132;      // 64 x 132
    float* Sc   = Vs + 64 * 132;      // 64 x 68
    float* mrow = Sc + 64 * 68;       // 64
    float* lrow = mrow + 64;          // 64
    float* cfac = lrow + 64;          // 64

    const int t  = threadIdx.x;
    const int q0 = blockIdx.x * 64;
    const int h  = blockIdx.y;
    const int b  = blockIdx.z;

    // Load Q tile: thread loads 16 floats (4 x float4), coalesced
    {
        const float* Qg = g_Q + ((long long)(h * B_ + b) * S_ + q0) * O_;
        int r = t >> 3, off = (t & 7) << 4;
#pragma unroll
        for (int i = 0; i < 4; i++)
            *(float4*)&Qs[r * 132 + off + i * 4] =
                *(const float4*)&Qg[(long long)r * O_ + off + i * 4];
    }
    if (t < 64) { mrow[t] = -1e30f; lrow[t] = 0.f; }

    const int ty = t >> 4, tx = t & 15;     // score phase mapping
    const int w = t >> 5, lane = t & 31;    // PV phase mapping
    const int o0 = lane << 2;

    float acc[4][4];
#pragma unroll
    for (int i = 0; i < 4; i++)
#pragma unroll
        for (int j = 0; j < 4; j++) acc[i][j] = 0.f;

    const float scale = 0.08838834764831845f; // 1/sqrt(128)
    const float* Kg = g_K + (long long)b * S_ * O_;
    const float* Vg = g_V + (long long)b * S_ * O_;

    for (int kt = 0; kt < S_; kt += 64) {
        __syncthreads();  // guard K/V/Sc reuse from previous iteration
        // Load K, V tiles
        {
            int r = t >> 3, off = (t & 7) << 4;
            const float* kp = &Kg[(long long)(kt + r) * O_ + off];
            const float* vp = &Vg[(long long)(kt + r) * O_ + off];
#pragma unroll
            for (int i = 0; i < 4; i++) {
                *(float4*)&Ks[r * 132 + off + i * 4] = *(const float4*)&kp[i * 4];
                *(float4*)&Vs[r * 132 + off + i * 4] = *(const float4*)&vp[i * 4];
            }
        }
        __syncthreads();

        // Scores: S[q][k] = Q[q] . K[k], thread does 2 q x 4 k
        {
            float s[2][4];
#pragma unroll
            for (int i = 0; i < 2; i++)
#pragma unroll
                for (int j = 0; j < 4; j++) s[i][j] = 0.f;
            const float* q0p = &Qs[(2 * ty) * 132];
            const float* q1p = &Qs[(2 * ty + 1) * 132];
#pragma unroll 4
            for (int o = 0; o < O_; o += 4) {
                float4 qa = *(const float4*)&q0p[o];
                float4 qb = *(const float4*)&q1p[o];
#pragma unroll
                for (int j = 0; j < 4; j++) {
                    float4 kv = *(const float4*)&Ks[(tx + 16 * j) * 132 + o];
                    s[0][j] += qa.x * kv.x + qa.y * kv.y + qa.z * kv.z + qa.w * kv.w;
                    s[1][j] += qb.x * kv.x + qb.y * kv.y + qb.z * kv.z + qb.w * kv.w;
                }
            }
#pragma unroll
            for (int i = 0; i < 2; i++)
#pragma unroll
                for (int j = 0; j < 4; j++)
                    Sc[(2 * ty + i) * 68 + tx + 16 * j] = s[i][j] * scale;
        }
        __syncthreads();

        // Online softmax row update (one thread per row)
        if (t < 64) {
            float mo = mrow[t];
            float mx = mo;
            float* sr = &Sc[t * 68];
#pragma unroll 8
            for (int j = 0; j < 64; j++) mx = fmaxf(mx, sr[j]);
            float c = __expf(mo - mx);
            float l = lrow[t] * c;
#pragma unroll 8
            for (int j = 0; j < 64; j++) {
                float p = __expf(sr[j] - mx);
                sr[j] = p;
                l += p;
            }
            mrow[t] = mx; lrow[t] = l; cfac[t] = c;
        }
        __syncthreads();

        // Rescale accumulators + PV: warp w owns q rows 4w..4w+3, lane owns 4 o's
        {
#pragma unroll
            for (int i = 0; i < 4; i++) {
                float c = cfac[4 * w + i];
                acc[i][0] *= c; acc[i][1] *= c; acc[i][2] *= c; acc[i][3] *= c;
            }
#pragma unroll 2
            for (int j0 = 0; j0 < 64; j0 += 4) {
                float4 v0 = *(const float4*)&Vs[(j0 + 0) * 132 + o0];
                float4 v1 = *(const float4*)&Vs[(j0 + 1) * 132 + o0];
                float4 v2 = *(const float4*)&Vs[(j0 + 2) * 132 + o0];
                float4 v3 = *(const float4*)&Vs[(j0 + 3) * 132 + o0];
#pragma unroll
                for (int i = 0; i < 4; i++) {
                    float4 p = *(const float4*)&Sc[(4 * w + i) * 68 + j0];
                    acc[i][0] += p.x * v0.x + p.y * v1.x + p.z * v2.x + p.w * v3.x;
                    acc[i][1] += p.x * v0.y + p.y * v1.y + p.z * v2.y + p.w * v3.y;
                    acc[i][2] += p.x * v0.z + p.y * v1.z + p.z * v2.z + p.w * v3.z;
                    acc[i][3] += p.x * v0.w + p.y * v1.w + p.z * v2.w + p.w * v3.w;
                }
            }
        }
    }
    __syncthreads();

    // Normalize and write ctx in (B,S,H,O) layout
#pragma unroll
    for (int i = 0; i < 4; i++) {
        int q = 4 * w + i;
        float inv = 1.0f / lrow[q];
        float4 r = make_float4(acc[i][0] * inv, acc[i][1] * inv,
                               acc[i][2] * inv, acc[i][3] * inv);
        float* cp = &g_ctx[(((long long)b * S_ + q0 + q) * H_ + h) * O_ + o0];
        *(float4*)cp = r;
    }
}

// ---------------------------------------------------------------------------
extern "C" void kernel_launch(void* const* d_in, const int* in_sizes, int n_in,
                              void* d_out, int out_size)
{
    const float* x  = (const float*)d_in[0];
    const float* Wq = (const float*)d_in[1];
    const float* Wk = (const float*)d_in[2];
    const float* Wv = (const float*)d_in[3];
    const float* Wo = (const float*)d_in[4];
    float* out = (float*)d_out;

    float *Qp, *Kp, *Vp, *Cp;
    cudaGetSymbolAddress((void**)&Qp, g_Q);
    cudaGetSymbolAddress((void**)&Kp, g_K);
    cudaGetSymbolAddress((void**)&Vp, g_V);
    cudaGetSymbolAddress((void**)&Cp, g_ctx);

    const size_t attn_smem = (size_t)ATTN_SMEM_FLOATS * sizeof(float);
    cudaFuncSetAttribute(attn_kernel,
                         cudaFuncAttributeMaxDynamicSharedMemorySize,
                         (int)attn_smem);

    const int M = B_ * S_;  // 8192

    // Q projection: per-head GEMM, output layout (H,B,S,O)
    sgemm_kernel<<<dim3(1, M / 64, H_), 256>>>(
        x, Wq, Qp, M, O_, E_, (long long)E_ * O_, (long long)B_ * S_ * O_);
    // K, V projections
    sgemm_kernel<<<dim3(1, M / 64, 1), 256>>>(x, Wk, Kp, M, O_, E_, 0, 0);
    sgemm_kernel<<<dim3(1, M / 64, 1), 256>>>(x, Wv, Vp, M, O_, E_, 0, 0);
    // Attention
    attn_kernel<<<dim3(S_ / 64, H_, B_), 512, attn_smem>>>();
    // Output projection: (B*S, H*O) @ (H*O, E)
    sgemm_kernel<<<dim3(E_ / 128, M / 64, 1), 256>>>(
        Cp, Wo, out, M, E_, H_ * O_, 0, 0);
}